// round 16
// baseline (speedup 1.0000x reference)
#include <cuda_runtime.h>

#define EDIM    4096
#define BATCH   8
#define HEADS   32
#define DHEAD   128
#define TPREV   2047
#define TTOT    2048
#define NSPLIT  8
#define TOK_PER_BLOCK 256   // 8 warps * 32 tokens

#define GEMV_THREADS 512
#define GEMV_SMEM (BATCH * EDIM * sizeof(float))   // 128 KB dynamic smem

// ---------------- scratch (device globals, no allocation) ----------------
__device__ float g_q[BATCH * EDIM];   // only rows 3968..4095 (head 31) valid
__device__ float g_k[BATCH * EDIM];
__device__ float g_v[BATCH * EDIM];
__device__ float g_attn[BATCH * EDIM];
__device__ float g_pm[BATCH * HEADS * NSPLIT];
__device__ float g_pl[BATCH * HEADS * NSPLIT];
__device__ float g_pacc[BATCH * HEADS * NSPLIT * DHEAD];
__device__ unsigned int g_cnt[BATCH * HEADS];   // split-arrival counters

// ---------------- packed f32x2 FMA helpers --------------------------------
__device__ __forceinline__ void ffma2(unsigned long long& d,
                                      unsigned long long a,
                                      unsigned long long b) {
    asm("fma.rn.f32x2 %0, %1, %2, %0;" : "+l"(d) : "l"(a), "l"(b));
}
__device__ __forceinline__ float unpack_sum(unsigned long long v) {
    float lo, hi;
    asm("mov.b64 {%0, %1}, %2;" : "=f"(lo), "=f"(hi) : "l"(v));
    return lo + hi;
}

// ---------------- GEMV mainloop: 32 rows, 16 warps, K-split, f32x2 --------
__device__ __forceinline__ void gemv_mainloop(const float* __restrict__ xs,
                                              const float* __restrict__ W,
                                              const float* __restrict__ bias,
                                              float* __restrict__ Y,
                                              int row0_blk) {
    __shared__ float buf[2][32][8];                // cross-half partials

    const int warp  = threadIdx.x >> 5;
    const int lane  = threadIdx.x & 31;
    const int wrow4 = warp & 7;                    // row group 0..7
    const int half  = warp >> 3;                   // K half 0..1
    const int row0  = row0_blk + wrow4 * 4;
    const int kbase = half * 2048;

    unsigned long long acc2[4][8];
#pragma unroll
    for (int r = 0; r < 4; ++r)
#pragma unroll
        for (int b = 0; b < 8; ++b) acc2[r][b] = 0ull;

    const float* w0 = W + (size_t)row0 * EDIM + kbase + lane * 4;

    // double-buffered W prefetch (wA = current, wB = next)
    ulonglong2 wA[4], wB[4];
#pragma unroll
    for (int r = 0; r < 4; ++r)
        wA[r] = *(const ulonglong2*)&w0[(size_t)r * EDIM];
#pragma unroll
    for (int r = 0; r < 4; ++r)
        wB[r] = *(const ulonglong2*)&w0[(size_t)r * EDIM + 128];

    // 16 macro-steps x 128 floats; prefetch ms+2 FIRST, then compute ms
#pragma unroll
    for (int ms = 0; ms < 16; ++ms) {
        ulonglong2 wC[4];
        if (ms < 14) {
#pragma unroll
            for (int r = 0; r < 4; ++r)
                wC[r] = *(const ulonglong2*)&w0[(size_t)r * EDIM + (ms + 2) * 128];
        }
        const int i = kbase + ms * 128 + lane * 4;
#pragma unroll
        for (int b = 0; b < 8; ++b) {
            const ulonglong2 xc = *(const ulonglong2*)&xs[b * EDIM + i];
#pragma unroll
            for (int r = 0; r < 4; ++r) {
                ffma2(acc2[r][b], wA[r].x, xc.x);
                ffma2(acc2[r][b], wA[r].y, xc.y);
            }
        }
#pragma unroll
        for (int r = 0; r < 4; ++r) { wA[r] = wB[r]; wB[r] = wC[r]; }
    }

    // unpack + warp-reduce 32 accumulators; lane = r*8+b holds its value
    float accs[4][8];
#pragma unroll
    for (int r = 0; r < 4; ++r)
#pragma unroll
        for (int b = 0; b < 8; ++b) {
            float v = unpack_sum(acc2[r][b]);
#pragma unroll
            for (int s = 16; s > 0; s >>= 1)
                v += __shfl_xor_sync(0xffffffffu, v, s);
            accs[r][b] = v;
        }
    {
        const int r = lane >> 3;
        const int b = lane & 7;
        buf[half][wrow4 * 4 + r][b] = accs[r][b];
    }
    __syncthreads();

    // merge the two K halves: 256 threads cover 32 rows x 8 batches
    if (threadIdx.x < 256) {
        const int rl = threadIdx.x >> 3;
        const int b  = threadIdx.x & 7;
        const int row = row0_blk + rl;
        Y[b * EDIM + row] = buf[0][rl][b] + buf[1][rl][b] + bias[row];
    }
}

// ---------------- q projection (head-31 slice) + counter reset -------------
__global__ __launch_bounds__(GEMV_THREADS)
void q_proj(const float* __restrict__ x,
            const float* __restrict__ Wq, const float* __restrict__ bq) {
    extern __shared__ float xs[];   // [BATCH * EDIM]

    if (blockIdx.x == 0 && threadIdx.x < BATCH * HEADS)
        g_cnt[threadIdx.x] = 0u;

#pragma unroll
    for (int t = threadIdx.x; t < 8192; t += GEMV_THREADS) {
        const int b = t >> 10;
        const int i = (t & 1023) * 4;
        *(float4*)&xs[b * EDIM + i] = *(const float4*)&x[b * EDIM + i];
    }
    __syncthreads();
    gemv_mainloop(xs, Wq, bq, g_q, (HEADS - 1) * DHEAD + blockIdx.x * 32);
}

// ---------------- k + v projections -----------------------------------------
__global__ __launch_bounds__(GEMV_THREADS)
void kv_proj(const float* __restrict__ x,
             const float* __restrict__ Wk, const float* __restrict__ bk,
             const float* __restrict__ Wv, const float* __restrict__ bv) {
    extern __shared__ float xs[];   // [BATCH * EDIM]
#pragma unroll
    for (int t = threadIdx.x; t < 8192; t += GEMV_THREADS) {
        const int b = t >> 10;
        const int i = (t & 1023) * 4;
        *(float4*)&xs[b * EDIM + i] = *(const float4*)&x[b * EDIM + i];
    }
    __syncthreads();

    if (blockIdx.x < 128)
        gemv_mainloop(xs, Wk, bk, g_k, blockIdx.x * 32);
    else
        gemv_mainloop(xs, Wv, bv, g_v, (blockIdx.x - 128) * 32);
}

// ---------------- output projection (stages g_attn, then GEMV) ------------
__global__ __launch_bounds__(GEMV_THREADS)
void out_gemv(const float* __restrict__ Wo,
              const float* __restrict__ bo,
              float* __restrict__ out) {
    extern __shared__ float xs[];   // [BATCH * EDIM]
#pragma unroll
    for (int t = threadIdx.x; t < 8192; t += GEMV_THREADS) {
        const int b = t >> 10;
        const int i = (t & 1023) * 4;
        *(float4*)&xs[b * EDIM + i] = *(const float4*)&g_attn[b * EDIM + i];
    }
    __syncthreads();
    gemv_mainloop(xs, Wo, bo, out, blockIdx.x * 32);
}

// ---------------- fused cache-copy + flash attention + inline combine -----
// split = blockIdx.x + split0.  attn_main: split0=0, gridDim.x=7 (tokens
// 0..1791, needs only q).  attn_last: split0=7, gridDim.x=1 (tokens
// 1792..2047 incl. the new token -> needs g_k/g_v).  The LAST block to
// finish across BOTH kernels for each (b,h) merges the 8 split partials.
__global__ void attn_kernel(const float* __restrict__ kc,
                            const float* __restrict__ vc,
                            float* __restrict__ kout,
                            float* __restrict__ vout,
                            int split0) {
    const int split = blockIdx.x + split0;
    const int h = blockIdx.y;
    const int b = blockIdx.z;
    const int warp = threadIdx.x >> 5;
    const int lane = threadIdx.x & 31;
    const int bh = b * HEADS + h;

    // q from head 31 for ALL heads (reference broadcast semantics)
    const float4 q4 = *(const float4*)&g_q[b * EDIM + (HEADS - 1) * DHEAD + lane * 4];
    const float scale = 0.08838834764831845f;  // 1/sqrt(128)

    float m = -1e30f, l = 0.f;
    float4 acc = make_float4(0.f, 0.f, 0.f, 0.f);

    const int tok0 = split * TOK_PER_BLOCK + warp * 32;

#pragma unroll 4
    for (int j = 0; j < 32; ++j) {
        const int tok = tok0 + j;
        const float* kp;
        const float* vp;
        if (tok < TPREV) {
            const size_t off = ((size_t)bh * TPREV + tok) * DHEAD;
            kp = kc + off;
            vp = vc + off;
        } else {
            kp = g_k + b * EDIM + h * DHEAD;
            vp = g_v + b * EDIM + h * DHEAD;
        }
        const float4 k4 = *(const float4*)&kp[lane * 4];
        const float4 v4 = *(const float4*)&vp[lane * 4];

        // cache copy rides the same read
        const size_t oo = ((size_t)bh * TTOT + tok) * DHEAD + lane * 4;
        *(float4*)&kout[oo] = k4;
        *(float4*)&vout[oo] = v4;

        float s = q4.x * k4.x + q4.y * k4.y + q4.z * k4.z + q4.w * k4.w;
#pragma unroll
        for (int sh = 16; sh > 0; sh >>= 1)
            s += __shfl_xor_sync(0xffffffffu, s, sh);
        s *= scale;

        const float mn = fmaxf(m, s);
        const float sc = __expf(m - mn);
        const float p  = __expf(s - mn);
        l = l * sc + p;
        acc.x = acc.x * sc + p * v4.x;
        acc.y = acc.y * sc + p * v4.y;
        acc.z = acc.z * sc + p * v4.z;
        acc.w = acc.w * sc + p * v4.w;
        m = mn;
    }

    // combine the 8 warps of this block
    __shared__ float sm_m[8], sm_l[8];
    __shared__ __align__(16) float sm_acc[8][DHEAD];
    __shared__ int s_last;
    if (lane == 0) { sm_m[warp] = m; sm_l[warp] = l; }
    *(float4*)&sm_acc[warp][lane * 4] = acc;
    __syncthreads();

    if (threadIdx.x < DHEAD) {
        const int d = threadIdx.x;
        float M = -1e30f;
#pragma unroll
        for (int w = 0; w < 8; ++w) M = fmaxf(M, sm_m[w]);
        float L = 0.f, A = 0.f;
#pragma unroll
        for (int w = 0; w < 8; ++w) {
            const float e = __expf(sm_m[w] - M);
            L += sm_l[w] * e;
            A += sm_acc[w][d] * e;
        }
        const int idx = bh * NSPLIT + split;
        g_pacc[idx * DHEAD + d] = A;
        if (d == 0) { g_pm[idx] = M; g_pl[idx] = L; }
    }
    __syncthreads();

    // last-arriving split block (across both attn kernels) combines
    if (threadIdx.x == 0) {
        __threadfence();
        s_last = (atomicAdd(&g_cnt[bh], 1u) == NSPLIT - 1);
    }
    __syncthreads();

    if (s_last && threadIdx.x < DHEAD) {
        __threadfence();   // acquire: see all 8 splits' partials
        const int d = threadIdx.x;
        float M = -1e30f;
#pragma unroll
        for (int s = 0; s < NSPLIT; ++s)
            M = fmaxf(M, g_pm[bh * NSPLIT + s]);
        float L = 0.f, A = 0.f;
#pragma unroll
        for (int s = 0; s < NSPLIT; ++s) {
            const float e = __expf(g_pm[bh * NSPLIT + s] - M);
            L += g_pl[bh * NSPLIT + s] * e;
            A += g_pacc[(bh * NSPLIT + s) * DHEAD + d] * e;
        }
        g_attn[b * EDIM + h * DHEAD + d] = A / L;
    }
}

// ---------------- launch ---------------------------------------------------
extern "C" void kernel_launch(void* const* d_in, const int* in_sizes, int n_in,
                              void* d_out, int out_size) {
    // Defensive input mapping based on element counts.
    const float *x, *kc, *vc, *Wq, *bq, *Wk, *bk, *Wv, *bv, *Wo, *bo;
    if (in_sizes[0] == BATCH * EDIM) {
        // signature/dict order: x, kc, vc, Wq, bq, Wk, bk, Wv, bv, Wo, bo
        x  = (const float*)d_in[0];
        kc = (const float*)d_in[1];
        vc = (const float*)d_in[2];
        Wq = (const float*)d_in[3];
        bq = (const float*)d_in[4];
        Wk = (const float*)d_in[5];
        bk = (const float*)d_in[6];
        Wv = (const float*)d_in[7];
        bv = (const float*)d_in[8];
        Wo = (const float*)d_in[9];
        bo = (const float*)d_in[10];
    } else {
        // alphabetical order: Wk, Wo, Wq, Wv, bk, bo, bq, bv, kc, vc, x
        Wk = (const float*)d_in[0];
        Wo = (const float*)d_in[1];
        Wq = (const float*)d_in[2];
        Wv = (const float*)d_in[3];
        bk = (const float*)d_in[4];
        bo = (const float*)d_in[5];
        bq = (const float*)d_in[6];
        bv = (const float*)d_in[7];
        kc = (const float*)d_in[8];
        vc = (const float*)d_in[9];
        x  = (const float*)d_in[10];
    }

    float* out  = (float*)d_out;                                   // [8,1,4096]
    float* kout = out + (size_t)BATCH * EDIM;                      // [8,32,2048,128]
    float* vout = kout + (size_t)BATCH * HEADS * TTOT * DHEAD;     // [8,32,2048,128]

    // one-time setup (first call is the pre-capture correctness run)
    static cudaStream_t s1 = nullptr;
    static cudaEvent_t eQ = nullptr, eA1 = nullptr;
    if (!s1) {
        cudaFuncSetAttribute(q_proj,   cudaFuncAttributeMaxDynamicSharedMemorySize, (int)GEMV_SMEM);
        cudaFuncSetAttribute(kv_proj,  cudaFuncAttributeMaxDynamicSharedMemorySize, (int)GEMV_SMEM);
        cudaFuncSetAttribute(out_gemv, cudaFuncAttributeMaxDynamicSharedMemorySize, (int)GEMV_SMEM);
        cudaStreamCreateWithFlags(&s1, cudaStreamNonBlocking);
        cudaEventCreateWithFlags(&eQ,  cudaEventDisableTiming);
        cudaEventCreateWithFlags(&eA1, cudaEventDisableTiming);
    }

    // default stream: q_proj -> (fork) kv_proj -> attn_last -> (join) -> out
    // side stream s1:           attn_main (splits 0..6; needs only q)
    q_proj<<<4, GEMV_THREADS, GEMV_SMEM>>>(x, Wq, bq);
    cudaEventRecord(eQ, 0);

    cudaStreamWaitEvent(s1, eQ, 0);
    attn_kernel<<<dim3(NSPLIT - 1, HEADS, BATCH), 256, 0, s1>>>(kc, vc, kout, vout, 0);
    cudaEventRecord(eA1, s1);

    kv_proj<<<256, GEMV_THREADS, GEMV_SMEM>>>(x, Wk, bk, Wv, bv);
    attn_kernel<<<dim3(1, HEADS, BATCH), 256>>>(kc, vc, kout, vout, NSPLIT - 1);

    cudaStreamWaitEvent(0, eA1, 0);
    out_gemv<<<128, GEMV_THREADS, GEMV_SMEM>>>(Wo, bo, out);
}

// round 17
// speedup vs baseline: 1.1022x; 1.1022x over previous
#include <cuda_runtime.h>

#define EDIM    4096
#define BATCH   8
#define HEADS   32
#define DHEAD   128
#define TPREV   2047
#define TTOT    2048
#define NSPLIT  8              // attention splits over cache tokens
#define NSPLIT_P 9             // + 1 partial from the new token
#define TOK_PER_BLOCK 256      // 8 warps * 32 tokens

#define GEMV_THREADS 512
#define GEMV_SMEM (BATCH * EDIM * sizeof(float))   // 128 KB dynamic smem

// ---------------- scratch (device globals, no allocation) ----------------
__device__ float g_q[BATCH * EDIM];   // only rows 3968..4095 (head 31) valid
__device__ float g_k[BATCH * EDIM];
__device__ float g_v[BATCH * EDIM];
__device__ float g_attn[BATCH * EDIM];
__device__ float g_pm[BATCH * HEADS * NSPLIT_P];
__device__ float g_pl[BATCH * HEADS * NSPLIT_P];
__device__ float g_pacc[BATCH * HEADS * NSPLIT_P * DHEAD];
__device__ unsigned int g_cnt[BATCH * HEADS];   // arrival counters (target 9)

// ---------------- packed f32x2 FMA helpers --------------------------------
__device__ __forceinline__ void ffma2(unsigned long long& d,
                                      unsigned long long a,
                                      unsigned long long b) {
    asm("fma.rn.f32x2 %0, %1, %2, %0;" : "+l"(d) : "l"(a), "l"(b));
}
__device__ __forceinline__ float unpack_sum(unsigned long long v) {
    float lo, hi;
    asm("mov.b64 {%0, %1}, %2;" : "=f"(lo), "=f"(hi) : "l"(v));
    return lo + hi;
}

// ---------------- GEMV mainloop: 32 rows, 16 warps, K-split, f32x2 --------
__device__ __forceinline__ void gemv_mainloop(const float* __restrict__ xs,
                                              const float* __restrict__ W,
                                              const float* __restrict__ bias,
                                              float* __restrict__ Y,
                                              int row0_blk) {
    __shared__ float buf[2][32][8];                // cross-half partials

    const int warp  = threadIdx.x >> 5;
    const int lane  = threadIdx.x & 31;
    const int wrow4 = warp & 7;                    // row group 0..7
    const int half  = warp >> 3;                   // K half 0..1
    const int row0  = row0_blk + wrow4 * 4;
    const int kbase = half * 2048;

    unsigned long long acc2[4][8];
#pragma unroll
    for (int r = 0; r < 4; ++r)
#pragma unroll
        for (int b = 0; b < 8; ++b) acc2[r][b] = 0ull;

    const float* w0 = W + (size_t)row0 * EDIM + kbase + lane * 4;

    ulonglong2 wA[4], wB[4];
#pragma unroll
    for (int r = 0; r < 4; ++r)
        wA[r] = *(const ulonglong2*)&w0[(size_t)r * EDIM];
#pragma unroll
    for (int r = 0; r < 4; ++r)
        wB[r] = *(const ulonglong2*)&w0[(size_t)r * EDIM + 128];

#pragma unroll
    for (int ms = 0; ms < 16; ++ms) {
        ulonglong2 wC[4];
        if (ms < 14) {
#pragma unroll
            for (int r = 0; r < 4; ++r)
                wC[r] = *(const ulonglong2*)&w0[(size_t)r * EDIM + (ms + 2) * 128];
        }
        const int i = kbase + ms * 128 + lane * 4;
#pragma unroll
        for (int b = 0; b < 8; ++b) {
            const ulonglong2 xc = *(const ulonglong2*)&xs[b * EDIM + i];
#pragma unroll
            for (int r = 0; r < 4; ++r) {
                ffma2(acc2[r][b], wA[r].x, xc.x);
                ffma2(acc2[r][b], wA[r].y, xc.y);
            }
        }
#pragma unroll
        for (int r = 0; r < 4; ++r) { wA[r] = wB[r]; wB[r] = wC[r]; }
    }

    float accs[4][8];
#pragma unroll
    for (int r = 0; r < 4; ++r)
#pragma unroll
        for (int b = 0; b < 8; ++b) {
            float v = unpack_sum(acc2[r][b]);
#pragma unroll
            for (int s = 16; s > 0; s >>= 1)
                v += __shfl_xor_sync(0xffffffffu, v, s);
            accs[r][b] = v;
        }
    {
        const int r = lane >> 3;
        const int b = lane & 7;
        buf[half][wrow4 * 4 + r][b] = accs[r][b];
    }
    __syncthreads();

    if (threadIdx.x < 256) {
        const int rl = threadIdx.x >> 3;
        const int b  = threadIdx.x & 7;
        const int row = row0_blk + rl;
        Y[b * EDIM + row] = buf[0][rl][b] + buf[1][rl][b] + bias[row];
    }
}

// ---------------- q projection (head-31 slice) + counter reset -------------
__global__ __launch_bounds__(GEMV_THREADS)
void q_proj(const float* __restrict__ x,
            const float* __restrict__ Wq, const float* __restrict__ bq) {
    extern __shared__ float xs[];   // [BATCH * EDIM]

    if (blockIdx.x == 0 && threadIdx.x < BATCH * HEADS)
        g_cnt[threadIdx.x] = 0u;

#pragma unroll
    for (int t = threadIdx.x; t < 8192; t += GEMV_THREADS) {
        const int b = t >> 10;
        const int i = (t & 1023) * 4;
        *(float4*)&xs[b * EDIM + i] = *(const float4*)&x[b * EDIM + i];
    }
    __syncthreads();
    gemv_mainloop(xs, Wq, bq, g_q, (HEADS - 1) * DHEAD + blockIdx.x * 32);
}

// ---------------- k + v projections ----------------------------------------
__global__ __launch_bounds__(GEMV_THREADS)
void kv_proj(const float* __restrict__ x,
             const float* __restrict__ Wk, const float* __restrict__ bk,
             const float* __restrict__ Wv, const float* __restrict__ bv) {
    extern __shared__ float xs[];   // [BATCH * EDIM]
#pragma unroll
    for (int t = threadIdx.x; t < 8192; t += GEMV_THREADS) {
        const int b = t >> 10;
        const int i = (t & 1023) * 4;
        *(float4*)&xs[b * EDIM + i] = *(const float4*)&x[b * EDIM + i];
    }
    __syncthreads();

    if (blockIdx.x < 128)
        gemv_mainloop(xs, Wk, bk, g_k, blockIdx.x * 32);
    else
        gemv_mainloop(xs, Wv, bv, g_v, (blockIdx.x - 128) * 32);
}

// ---------------- output projection (stages g_attn, then GEMV) ------------
__global__ __launch_bounds__(GEMV_THREADS)
void out_gemv(const float* __restrict__ Wo,
              const float* __restrict__ bo,
              float* __restrict__ out) {
    extern __shared__ float xs[];   // [BATCH * EDIM]
#pragma unroll
    for (int t = threadIdx.x; t < 8192; t += GEMV_THREADS) {
        const int b = t >> 10;
        const int i = (t & 1023) * 4;
        *(float4*)&xs[b * EDIM + i] = *(const float4*)&g_attn[b * EDIM + i];
    }
    __syncthreads();
    gemv_mainloop(xs, Wo, bo, out, blockIdx.x * 32);
}

// ---------------- shared combine: 9 partials -> g_attn ---------------------
__device__ __forceinline__ void try_combine(int bh, int b, int h,
                                            int* s_last_ptr) {
    if (threadIdx.x == 0) {
        __threadfence();
        *s_last_ptr = (atomicAdd(&g_cnt[bh], 1u) == NSPLIT_P - 1);
    }
    __syncthreads();
    if (*s_last_ptr && threadIdx.x < DHEAD) {
        __threadfence();   // acquire: see all 9 partials
        const int d = threadIdx.x;
        float M = -1e30f;
#pragma unroll
        for (int s = 0; s < NSPLIT_P; ++s)
            M = fmaxf(M, g_pm[bh * NSPLIT_P + s]);
        float L = 0.f, A = 0.f;
#pragma unroll
        for (int s = 0; s < NSPLIT_P; ++s) {
            const float e = __expf(g_pm[bh * NSPLIT_P + s] - M);
            L += g_pl[bh * NSPLIT_P + s] * e;
            A += g_pacc[(bh * NSPLIT_P + s) * DHEAD + d] * e;
        }
        g_attn[b * EDIM + h * DHEAD + d] = A / L;
    }
}

// ---------------- flash attention over CACHE tokens only (0..2046) --------
// grid (NSPLIT, HEADS, BATCH), block 256. Depends ONLY on g_q — runs
// concurrently with kv_proj. Split 7 covers 255 tokens (2047 excluded).
// NOTE: the reference slices q AFTER transposing to (b,h,s,d), so
// q[:, -1:] selects the LAST HEAD (h=31), broadcast to all heads.
__global__ void attn_kernel(const float* __restrict__ kc,
                            const float* __restrict__ vc,
                            float* __restrict__ kout,
                            float* __restrict__ vout) {
    const int split = blockIdx.x;
    const int h = blockIdx.y;
    const int b = blockIdx.z;
    const int warp = threadIdx.x >> 5;
    const int lane = threadIdx.x & 31;
    const int bh = b * HEADS + h;

    const float4 q4 = *(const float4*)&g_q[b * EDIM + (HEADS - 1) * DHEAD + lane * 4];
    const float scale = 0.08838834764831845f;  // 1/sqrt(128)

    float m = -1e30f, l = 0.f;
    float4 acc = make_float4(0.f, 0.f, 0.f, 0.f);

    const int tok0 = split * TOK_PER_BLOCK + warp * 32;

#pragma unroll 4
    for (int j = 0; j < 32; ++j) {
        const int tok = tok0 + j;
        if (tok >= TPREV) break;     // only the very last warp hits this
        const size_t off = ((size_t)bh * TPREV + tok) * DHEAD;
        const float4 k4 = *(const float4*)&kc[off + lane * 4];
        const float4 v4 = *(const float4*)&vc[off + lane * 4];

        // cache copy rides the same read
        const size_t oo = ((size_t)bh * TTOT + tok) * DHEAD + lane * 4;
        *(float4*)&kout[oo] = k4;
        *(float4*)&vout[oo] = v4;

        float s = q4.x * k4.x + q4.y * k4.y + q4.z * k4.z + q4.w * k4.w;
#pragma unroll
        for (int sh = 16; sh > 0; sh >>= 1)
            s += __shfl_xor_sync(0xffffffffu, s, sh);
        s *= scale;

        const float mn = fmaxf(m, s);
        const float sc = __expf(m - mn);
        const float p  = __expf(s - mn);
        l = l * sc + p;
        acc.x = acc.x * sc + p * v4.x;
        acc.y = acc.y * sc + p * v4.y;
        acc.z = acc.z * sc + p * v4.z;
        acc.w = acc.w * sc + p * v4.w;
        m = mn;
    }

    // combine the 8 warps of this block
    __shared__ float sm_m[8], sm_l[8];
    __shared__ __align__(16) float sm_acc[8][DHEAD];
    __shared__ int s_last;
    if (lane == 0) { sm_m[warp] = m; sm_l[warp] = l; }
    *(float4*)&sm_acc[warp][lane * 4] = acc;
    __syncthreads();

    if (threadIdx.x < DHEAD) {
        const int d = threadIdx.x;
        float M = -1e30f;
#pragma unroll
        for (int w = 0; w < 8; ++w) M = fmaxf(M, sm_m[w]);
        float L = 0.f, A = 0.f;
#pragma unroll
        for (int w = 0; w < 8; ++w) {
            const float e = __expf(sm_m[w] - M);
            L += sm_l[w] * e;
            A += sm_acc[w][d] * e;
        }
        const int idx = bh * NSPLIT_P + split;
        g_pacc[idx * DHEAD + d] = A;
        if (d == 0) { g_pm[idx] = M; g_pl[idx] = L; }
    }
    __syncthreads();

    try_combine(bh, b, h, &s_last);
}

// ---------------- new-token partial (9th split) + cache row 2047 ----------
// grid (HEADS, BATCH), 128 threads. Runs after kv_proj.
__global__ void newtok_kernel(float* __restrict__ kout,
                              float* __restrict__ vout) {
    const int h = blockIdx.x;
    const int b = blockIdx.y;
    const int bh = b * HEADS + h;
    const int d = threadIdx.x;           // 0..127
    const int warp = d >> 5;
    const int lane = d & 31;
    __shared__ float ws[4];
    __shared__ int s_last;

    const float kv = g_k[b * EDIM + h * DHEAD + d];
    const float vv = g_v[b * EDIM + h * DHEAD + d];
    const float qv = g_q[b * EDIM + (HEADS - 1) * DHEAD + d];

    // cache row 2047
    kout[((size_t)bh * TTOT + TPREV) * DHEAD + d] = kv;
    vout[((size_t)bh * TTOT + TPREV) * DHEAD + d] = vv;

    // s = (q . k_new) * scale
    float p = qv * kv;
#pragma unroll
    for (int s = 16; s > 0; s >>= 1)
        p += __shfl_xor_sync(0xffffffffu, p, s);
    if (lane == 0) ws[warp] = p;
    __syncthreads();
    const float sc = (ws[0] + ws[1] + ws[2] + ws[3]) * 0.08838834764831845f;

    const int idx = bh * NSPLIT_P + NSPLIT;   // 9th partial slot
    g_pacc[idx * DHEAD + d] = vv;             // pacc = exp(0) * v_new
    if (d == 0) { g_pm[idx] = sc; g_pl[idx] = 1.0f; }
    __syncthreads();

    try_combine(bh, b, h, &s_last);
}

// ---------------- launch ---------------------------------------------------
extern "C" void kernel_launch(void* const* d_in, const int* in_sizes, int n_in,
                              void* d_out, int out_size) {
    const float *x, *kc, *vc, *Wq, *bq, *Wk, *bk, *Wv, *bv, *Wo, *bo;
    if (in_sizes[0] == BATCH * EDIM) {
        x  = (const float*)d_in[0];
        kc = (const float*)d_in[1];
        vc = (const float*)d_in[2];
        Wq = (const float*)d_in[3];
        bq = (const float*)d_in[4];
        Wk = (const float*)d_in[5];
        bk = (const float*)d_in[6];
        Wv = (const float*)d_in[7];
        bv = (const float*)d_in[8];
        Wo = (const float*)d_in[9];
        bo = (const float*)d_in[10];
    } else {
        Wk = (const float*)d_in[0];
        Wo = (const float*)d_in[1];
        Wq = (const float*)d_in[2];
        Wv = (const float*)d_in[3];
        bk = (const float*)d_in[4];
        bo = (const float*)d_in[5];
        bq = (const float*)d_in[6];
        bv = (const float*)d_in[7];
        kc = (const float*)d_in[8];
        vc = (const float*)d_in[9];
        x  = (const float*)d_in[10];
    }

    float* out  = (float*)d_out;                                   // [8,1,4096]
    float* kout = out + (size_t)BATCH * EDIM;                      // [8,32,2048,128]
    float* vout = kout + (size_t)BATCH * HEADS * TTOT * DHEAD;     // [8,32,2048,128]

    static cudaStream_t s1 = nullptr;
    static cudaEvent_t eQ = nullptr, eA1 = nullptr;
    if (!s1) {
        cudaFuncSetAttribute(q_proj,   cudaFuncAttributeMaxDynamicSharedMemorySize, (int)GEMV_SMEM);
        cudaFuncSetAttribute(kv_proj,  cudaFuncAttributeMaxDynamicSharedMemorySize, (int)GEMV_SMEM);
        cudaFuncSetAttribute(out_gemv, cudaFuncAttributeMaxDynamicSharedMemorySize, (int)GEMV_SMEM);
        cudaStreamCreateWithFlags(&s1, cudaStreamNonBlocking);
        cudaEventCreateWithFlags(&eQ,  cudaEventDisableTiming);
        cudaEventCreateWithFlags(&eA1, cudaEventDisableTiming);
    }

    // default: q_proj -> kv_proj -> newtok -> (wait attn) -> out_gemv
    // s1:      (wait q) attn over cache tokens (needs only q)
    q_proj<<<4, GEMV_THREADS, GEMV_SMEM>>>(x, Wq, bq);
    cudaEventRecord(eQ, 0);

    cudaStreamWaitEvent(s1, eQ, 0);
    attn_kernel<<<dim3(NSPLIT, HEADS, BATCH), 256, 0, s1>>>(kc, vc, kout, vout);
    cudaEventRecord(eA1, s1);

    kv_proj<<<256, GEMV_THREADS, GEMV_SMEM>>>(x, Wk, bk, Wv, bv);
    newtok_kernel<<<dim3(HEADS, BATCH), 128>>>(kout, vout);

    cudaStreamWaitEvent(0, eA1, 0);
    out_gemv<<<128, GEMV_THREADS, GEMV_SMEM>>>(Wo, bo, out);
}